// round 1
// baseline (speedup 1.0000x reference)
#include <cuda_runtime.h>
#include <math.h>

#define NN 200000
#define EE 1600000
#define CC 128
#define NTTS 20000
#define NMOLS 2000

// ---------------- static device scratch (no allocations allowed) ----------------
__device__ float g_t1[(size_t)NN * CC];
__device__ float g_t2[(size_t)NN * CC];
__device__ float g_hs[(size_t)NN * CC];
__device__ float g_hs2[(size_t)NTTS * CC];
__device__ int   g_cnt[NN];
__device__ int   g_rowoff[NN + 1];
__device__ int   g_cursor[NN];
__device__ int   g_bsum[256];
__device__ int   g_col[EE];
__device__ float g_val[EE];
__device__ int   g_ttoff[NTTS + 1];
__device__ int   g_moloff[NMOLS + 1];
__device__ float g_meanbn_tt[(size_t)NTTS * CC];
__device__ float g_gatout_tt[(size_t)NTTS * CC];
__device__ float g_gi_tt[(size_t)NTTS * 3 * CC];
__device__ float g_gh_tt[(size_t)NTTS * 3 * CC];
__device__ float g_ttbn[(size_t)NTTS * CC];
__device__ float g_meanbn_mol[(size_t)NMOLS * CC];
__device__ float g_gatout_mol[(size_t)NMOLS * CC];
__device__ float g_gi_mol[(size_t)NMOLS * 3 * CC];
__device__ float g_gh_mol[(size_t)NMOLS * 3 * CC];
__device__ float g_molout[(size_t)NMOLS * CC];
__device__ float g_ssrc[NN];
__device__ float g_sdst[NTTS];
__device__ float g_vd[CC];

// ---------------- small helpers ----------------
__device__ __forceinline__ float bn_apply(float x, int idx, int ch,
                                          const float* g, const float* b,
                                          const float* m, const float* v) {
    float sc = g[idx * CC + ch] * rsqrtf(v[idx * CC + ch] + 1e-5f);
    return (x - m[idx * CC + ch]) * sc + b[idx * CC + ch];
}
__device__ __forceinline__ float warp_max(float v) {
#pragma unroll
    for (int o = 16; o > 0; o >>= 1) v = fmaxf(v, __shfl_xor_sync(0xffffffffu, v, o));
    return v;
}
__device__ __forceinline__ float warp_sum(float v) {
#pragma unroll
    for (int o = 16; o > 0; o >>= 1) v += __shfl_xor_sync(0xffffffffu, v, o);
    return v;
}

// ---------------- CSR build ----------------
__global__ void k_zero_int(int* p, int n) {
    int i = blockIdx.x * blockDim.x + threadIdx.x;
    if (i < n) p[i] = 0;
}
__global__ void k_hist(const int* __restrict__ idx0, int* __restrict__ cnt) {
    int e = blockIdx.x * blockDim.x + threadIdx.x;
    if (e < EE) atomicAdd(&cnt[idx0[e]], 1);
}
__global__ void k_scan1(const int* __restrict__ in, int* __restrict__ out,
                        int* __restrict__ bsum, int n) {
    __shared__ int sm[1024];
    int i = blockIdx.x * 1024 + threadIdx.x;
    int v = (i < n) ? in[i] : 0;
    sm[threadIdx.x] = v;
    __syncthreads();
    for (int off = 1; off < 1024; off <<= 1) {
        int t = (threadIdx.x >= off) ? sm[threadIdx.x - off] : 0;
        __syncthreads();
        sm[threadIdx.x] += t;
        __syncthreads();
    }
    if (i < n) out[i] = sm[threadIdx.x] - v;  // exclusive
    if (threadIdx.x == 1023) bsum[blockIdx.x] = sm[1023];
}
__global__ void k_scan2(int* __restrict__ bsum, int nb) {
    __shared__ int sm[256];
    int v = (threadIdx.x < nb) ? bsum[threadIdx.x] : 0;
    sm[threadIdx.x] = v;
    __syncthreads();
    for (int off = 1; off < 256; off <<= 1) {
        int t = (threadIdx.x >= off) ? sm[threadIdx.x - off] : 0;
        __syncthreads();
        sm[threadIdx.x] += t;
        __syncthreads();
    }
    if (threadIdx.x < nb) bsum[threadIdx.x] = sm[threadIdx.x] - v;  // exclusive
}
__global__ void k_scan3(int* __restrict__ out, const int* __restrict__ bsum,
                        int n, int total, int* __restrict__ cursor) {
    int i = blockIdx.x * 1024 + threadIdx.x;
    if (i < n) {
        int v = out[i] + bsum[blockIdx.x];
        out[i] = v;
        cursor[i] = v;
    }
    if (i == 0) out[n] = total;
}
__global__ void k_scatter(const int* __restrict__ adj, const float* __restrict__ aval,
                          int* __restrict__ cursor, int* __restrict__ col,
                          float* __restrict__ val) {
    int e = blockIdx.x * blockDim.x + threadIdx.x;
    if (e >= EE) return;
    int r = adj[e];
    int p = atomicAdd(&cursor[r], 1);
    col[p] = adj[EE + e];
    val[p] = aval[e];
}
// offsets for a sorted segment array
__global__ void k_segoff(const int* __restrict__ seg, int n, int nseg, int* __restrict__ off) {
    int i = blockIdx.x * blockDim.x + threadIdx.x;
    if (i >= n) return;
    int s = seg[i];
    int p = (i == 0) ? -1 : seg[i - 1];
    for (int t = p + 1; t <= s; ++t) off[t] = i;
    if (i == n - 1)
        for (int t = s + 1; t <= nseg; ++t) off[t] = n;
}

// ---------------- GEMM: Y[M,Nout] = X[M,128] @ W[Nout,128]^T (+bias), optional
// fused per-row dot with avec -> aout (used for GAT s_src). Weight-stationary,
// persistent blocks, 64x128 tile per block, 4x8 per thread. ----------------
#define GEMM_SMEM ((128 * 128 + 64 * 132) * 4)
__global__ __launch_bounds__(256, 2) void k_gemm(
    const float* __restrict__ X, const float* __restrict__ W,
    const float* __restrict__ bias, float* __restrict__ Y, int M, int Nout,
    const float* __restrict__ avec, float* __restrict__ aout) {
    extern __shared__ float sm[];
    float* Ws = sm;                 // [128][128]  (k-major transposed)
    float* Xs = sm + 128 * 128;     // [64][132]
    int tid = threadIdx.x;
    int ct = blockIdx.y;
    // load W tile transposed: Ws[k*128+o] = W[(ct*128+o)*128 + k]
    for (int idx = tid; idx < 128 * 32; idx += 256) {
        int o = idx & 127, kq = idx >> 7;
        float4 w4 = *reinterpret_cast<const float4*>(&W[(size_t)(ct * 128 + o) * 128 + kq * 4]);
        Ws[(kq * 4 + 0) * 128 + o] = w4.x;
        Ws[(kq * 4 + 1) * 128 + o] = w4.y;
        Ws[(kq * 4 + 2) * 128 + o] = w4.z;
        Ws[(kq * 4 + 3) * 128 + o] = w4.w;
    }
    int tx = tid & 15, ty = tid >> 4;
    int ntiles = (M + 63) >> 6;
    for (int tile = blockIdx.x; tile < ntiles; tile += gridDim.x) {
        __syncthreads();  // protect Xs / red from previous iteration
        int row0 = tile * 64;
        for (int idx = tid; idx < 64 * 32; idx += 256) {
            int m = idx >> 5, kq = idx & 31;
            int r = row0 + m;
            float4 v = make_float4(0.f, 0.f, 0.f, 0.f);
            if (r < M) v = *reinterpret_cast<const float4*>(&X[(size_t)r * 128 + kq * 4]);
            *reinterpret_cast<float4*>(&Xs[m * 132 + kq * 4]) = v;
        }
        __syncthreads();
        float acc[4][8];
#pragma unroll
        for (int i = 0; i < 4; i++)
#pragma unroll
            for (int j = 0; j < 8; j++) acc[i][j] = 0.f;
#pragma unroll 4
        for (int k = 0; k < 128; k++) {
            float a[4];
#pragma unroll
            for (int i = 0; i < 4; i++) a[i] = Xs[(ty * 4 + i) * 132 + k];
            float4 b0 = *reinterpret_cast<const float4*>(&Ws[k * 128 + tx * 8]);
            float4 b1 = *reinterpret_cast<const float4*>(&Ws[k * 128 + tx * 8 + 4]);
            float b[8] = {b0.x, b0.y, b0.z, b0.w, b1.x, b1.y, b1.z, b1.w};
#pragma unroll
            for (int i = 0; i < 4; i++)
#pragma unroll
                for (int j = 0; j < 8; j++) acc[i][j] += a[i] * b[j];
        }
        // epilogue: bias + store (vectorized)
#pragma unroll
        for (int i = 0; i < 4; i++) {
            int r = row0 + ty * 4 + i;
            if (r < M) {
                float v[8];
#pragma unroll
                for (int j = 0; j < 8; j++) {
                    int o = ct * 128 + tx * 8 + j;
                    v[j] = acc[i][j] + (bias ? bias[o] : 0.f);
                }
                float* yp = &Y[(size_t)r * Nout + ct * 128 + tx * 8];
                *reinterpret_cast<float4*>(yp) = make_float4(v[0], v[1], v[2], v[3]);
                *reinterpret_cast<float4*>(yp + 4) = make_float4(v[4], v[5], v[6], v[7]);
            }
        }
        if (avec) {  // fused s_src[r] = sum_o Y[r][o]*avec[o]  (Nout==128, ct==0)
            __syncthreads();
            float* red = Xs;
#pragma unroll
            for (int i = 0; i < 4; i++) {
                float p = 0.f;
#pragma unroll
                for (int j = 0; j < 8; j++) p += acc[i][j] * avec[tx * 8 + j];
                red[(ty * 4 + i) * 16 + tx] = p;
            }
            __syncthreads();
            if (tid < 64) {
                int r = row0 + tid;
                if (r < M) {
                    float s = 0.f;
#pragma unroll
                    for (int q = 0; q < 16; q++) s += red[tid * 16 + q];
                    aout[r] = s;
                }
            }
        }
    }
}

// ---------------- SpMM gather (warp/row) + fused bias + BN(+relu)(+BN2) ----------------
__global__ void k_spmm(const float* __restrict__ Xin, float* __restrict__ Y,
                       const int* __restrict__ rowoff, const int* __restrict__ col,
                       const float* __restrict__ val, const float* __restrict__ bias,
                       const float* __restrict__ bg, const float* __restrict__ bb,
                       const float* __restrict__ bm, const float* __restrict__ bv,
                       int bnA, int bnB, int M) {
    int gw = (blockIdx.x * blockDim.x + threadIdx.x) >> 5;
    int lane = threadIdx.x & 31;
    if (gw >= M) return;
    int s = rowoff[gw], e = rowoff[gw + 1];
    float acc[4] = {0.f, 0.f, 0.f, 0.f};
    for (int i = s; i < e; i++) {
        int c = col[i];
        float v = val[i];
        const float* xr = Xin + (size_t)c * CC;
#pragma unroll
        for (int j = 0; j < 4; j++) acc[j] += v * xr[lane + 32 * j];
    }
    float* yr = Y + (size_t)gw * CC;
#pragma unroll
    for (int j = 0; j < 4; j++) {
        int ch = lane + 32 * j;
        float z = acc[j] + bias[ch];
        z = bn_apply(z, bnA, ch, bg, bb, bm, bv);
        z = fmaxf(z, 0.f);
        if (bnB >= 0) z = bn_apply(z, bnB, ch, bg, bb, bm, bv);
        yr[ch] = z;
    }
}

// ---------------- segment sum pool (warp/segment) + relu + BN ----------------
__global__ void k_segpool(const float* __restrict__ X, float* __restrict__ Y,
                          const int* __restrict__ off, int nseg,
                          const float* bg, const float* bb, const float* bm,
                          const float* bv, int bi) {
    int gw = (blockIdx.x * blockDim.x + threadIdx.x) >> 5;
    int lane = threadIdx.x & 31;
    if (gw >= nseg) return;
    int s = off[gw], e = off[gw + 1];
    float acc[4] = {0.f, 0.f, 0.f, 0.f};
    for (int i = s; i < e; i++) {
        const float* xr = X + (size_t)i * CC;
#pragma unroll
        for (int j = 0; j < 4; j++) acc[j] += xr[lane + 32 * j];
    }
    float* yr = Y + (size_t)gw * CC;
#pragma unroll
    for (int j = 0; j < 4; j++) {
        int ch = lane + 32 * j;
        float z = fmaxf(acc[j], 0.f);
        yr[ch] = bn_apply(z, bi, ch, bg, bb, bm, bv);
    }
}

// vd[c] = sum_o adst[o] * Wdst[o,c]
__global__ void k_vd(const float* __restrict__ Wd, const float* __restrict__ ad,
                     float* __restrict__ vd) {
    int c = threadIdx.x;
    float s = 0.f;
    for (int o = 0; o < CC; o++) s += ad[o] * Wd[o * CC + c];
    vd[c] = s;
}
// out[r] = dot(X[r], v)
__global__ void k_rowdot(const float* __restrict__ X, const float* __restrict__ v,
                         float* __restrict__ out, int M) {
    int gw = (blockIdx.x * blockDim.x + threadIdx.x) >> 5;
    int lane = threadIdx.x & 31;
    if (gw >= M) return;
    const float* xr = X + (size_t)gw * CC;
    float s = 0.f;
#pragma unroll
    for (int j = 0; j < 4; j++) s += xr[lane + 32 * j] * v[lane + 32 * j];
    s = warp_sum(s);
    if (lane == 0) out[gw] = s;
}

// ---------------- GAT segment softmax + weighted aggregate + bias + ELU ----------------
__global__ void k_gat(const float* __restrict__ hs, const float* __restrict__ ssrc,
                      const float* __restrict__ sdst, const int* __restrict__ off,
                      const float* __restrict__ bias, float* __restrict__ out, int nseg) {
    int gw = (blockIdx.x * blockDim.x + threadIdx.x) >> 5;
    int lane = threadIdx.x & 31;
    if (gw >= nseg) return;
    int s = off[gw], e = off[gw + 1];
    float sd = sdst[gw];
    float acc[4] = {0.f, 0.f, 0.f, 0.f};
    if (e > s) {
        float mx = -3.402823e38f;
        for (int i = s + lane; i < e; i += 32) {
            float a = ssrc[i] + sd;
            a = a > 0.f ? a : 0.01f * a;
            mx = fmaxf(mx, a);
        }
        mx = warp_max(mx);
        float den = 0.f;
        for (int i = s + lane; i < e; i += 32) {
            float a = ssrc[i] + sd;
            a = a > 0.f ? a : 0.01f * a;
            den += __expf(a - mx);
        }
        den = warp_sum(den);
        float inv = 1.f / den;
        for (int i = s; i < e; i++) {
            float a = ssrc[i] + sd;
            a = a > 0.f ? a : 0.01f * a;
            float w = __expf(a - mx) * inv;
            const float* hr = hs + (size_t)i * CC;
#pragma unroll
            for (int j = 0; j < 4; j++) acc[j] += w * hr[lane + 32 * j];
        }
    }
    float* yr = out + (size_t)gw * CC;
#pragma unroll
    for (int j = 0; j < 4; j++) {
        int ch = lane + 32 * j;
        float v = acc[j] + bias[ch];
        v = v > 0.f ? v : (__expf(v) - 1.f);  // ELU
        yr[ch] = v;
    }
}

// ---------------- GRU gates + relu + BN(+BN2) ----------------
__global__ void k_gru(const float* __restrict__ gi, const float* __restrict__ gh,
                      const float* __restrict__ h, float* __restrict__ out, int M,
                      const float* bg, const float* bb, const float* bm,
                      const float* bv, int bnA, int bnB) {
    int idx = blockIdx.x * blockDim.x + threadIdx.x;
    if (idx >= M * CC) return;
    int t = idx >> 7, c = idx & 127;
    const float* gir = gi + (size_t)t * 3 * CC;
    const float* ghr = gh + (size_t)t * 3 * CC;
    float r = 1.f / (1.f + __expf(-(gir[c] + ghr[c])));
    float z = 1.f / (1.f + __expf(-(gir[CC + c] + ghr[CC + c])));
    float n = tanhf(gir[2 * CC + c] + r * ghr[2 * CC + c]);
    float hv = (1.f - z) * n + z * h[idx];
    float y = fmaxf(hv, 0.f);
    y = bn_apply(y, bnA, c, bg, bb, bm, bv);
    if (bnB >= 0) y = bn_apply(y, bnB, c, bg, bb, bm, bv);
    out[idx] = y;
}

// ---------------- predictor: relu(mol@W1^T+b1)@W2^T+b2 ----------------
__global__ void k_pred(const float* __restrict__ mol, const float* __restrict__ W1,
                       const float* __restrict__ b1, const float* __restrict__ W2,
                       const float* __restrict__ b2, float* __restrict__ out) {
    __shared__ float xr[CC];
    __shared__ float hr[64];
    int m = blockIdx.x, t = threadIdx.x;
    xr[t] = mol[(size_t)m * CC + t];
    xr[t + 64] = mol[(size_t)m * CC + t + 64];
    __syncthreads();
    float s = b1[t];
    for (int c = 0; c < CC; c++) s += W1[t * CC + c] * xr[c];
    s = fmaxf(s, 0.f);
    hr[t] = s * W2[t];
    __syncthreads();
    for (int off = 32; off > 0; off >>= 1) {
        if (t < off) hr[t] += hr[t + off];
        __syncthreads();
    }
    if (t == 0) out[m] = hr[0] + b2[0];
}

// ---------------- host ----------------
extern "C" void kernel_launch(void* const* d_in, const int* in_sizes, int n_in,
                              void* d_out, int out_size) {
    if (n_in < 24) return;
    const float *node_attr, *adj_value, *W_gcn, *b_gcn, *bg, *bb, *bm, *bv;
    const float *Wsrc, *Wdst, *asrc, *adst, *gbias, *Wih, *Whh, *bih, *bhh;
    const float *pW1, *pb1, *pW2, *pb2;
    const int *adj_index, *ttb, *tgb;
    if (in_sizes[1] == EE) {  // reference-signature order
        node_attr = (const float*)d_in[0];  adj_value = (const float*)d_in[1];
        W_gcn = (const float*)d_in[2];      b_gcn = (const float*)d_in[3];
        bg = (const float*)d_in[4];         bb = (const float*)d_in[5];
        bm = (const float*)d_in[6];         bv = (const float*)d_in[7];
        Wsrc = (const float*)d_in[8];       Wdst = (const float*)d_in[9];
        asrc = (const float*)d_in[10];      adst = (const float*)d_in[11];
        gbias = (const float*)d_in[12];     Wih = (const float*)d_in[13];
        Whh = (const float*)d_in[14];       bih = (const float*)d_in[15];
        bhh = (const float*)d_in[16];       pW1 = (const float*)d_in[17];
        pb1 = (const float*)d_in[18];       pW2 = (const float*)d_in[19];
        pb2 = (const float*)d_in[20];       adj_index = (const int*)d_in[21];
        ttb = (const int*)d_in[22];         tgb = (const int*)d_in[23];
    } else {  // setup_inputs dict order
        node_attr = (const float*)d_in[0];  adj_index = (const int*)d_in[1];
        adj_value = (const float*)d_in[2];  ttb = (const int*)d_in[3];
        tgb = (const int*)d_in[4];          W_gcn = (const float*)d_in[5];
        b_gcn = (const float*)d_in[6];      bg = (const float*)d_in[7];
        bb = (const float*)d_in[8];         bm = (const float*)d_in[9];
        bv = (const float*)d_in[10];        Wsrc = (const float*)d_in[11];
        Wdst = (const float*)d_in[12];      asrc = (const float*)d_in[13];
        adst = (const float*)d_in[14];      gbias = (const float*)d_in[15];
        Wih = (const float*)d_in[16];       Whh = (const float*)d_in[17];
        bih = (const float*)d_in[18];       bhh = (const float*)d_in[19];
        pW1 = (const float*)d_in[20];       pb1 = (const float*)d_in[21];
        pW2 = (const float*)d_in[22];       pb2 = (const float*)d_in[23];
    }

    void* p;
    cudaGetSymbolAddress(&p, g_t1);        float* t1 = (float*)p;
    cudaGetSymbolAddress(&p, g_t2);        float* t2 = (float*)p;
    cudaGetSymbolAddress(&p, g_hs);        float* hs = (float*)p;
    cudaGetSymbolAddress(&p, g_hs2);       float* hs2 = (float*)p;
    cudaGetSymbolAddress(&p, g_cnt);       int* cnt = (int*)p;
    cudaGetSymbolAddress(&p, g_rowoff);    int* rowoff = (int*)p;
    cudaGetSymbolAddress(&p, g_cursor);    int* cursor = (int*)p;
    cudaGetSymbolAddress(&p, g_bsum);      int* bsum = (int*)p;
    cudaGetSymbolAddress(&p, g_col);       int* col = (int*)p;
    cudaGetSymbolAddress(&p, g_val);       float* val = (float*)p;
    cudaGetSymbolAddress(&p, g_ttoff);     int* ttoff = (int*)p;
    cudaGetSymbolAddress(&p, g_moloff);    int* moloff = (int*)p;
    cudaGetSymbolAddress(&p, g_meanbn_tt); float* meanbn_tt = (float*)p;
    cudaGetSymbolAddress(&p, g_gatout_tt); float* gatout_tt = (float*)p;
    cudaGetSymbolAddress(&p, g_gi_tt);     float* gi_tt = (float*)p;
    cudaGetSymbolAddress(&p, g_gh_tt);     float* gh_tt = (float*)p;
    cudaGetSymbolAddress(&p, g_ttbn);      float* ttbn = (float*)p;
    cudaGetSymbolAddress(&p, g_meanbn_mol);float* meanbn_mol = (float*)p;
    cudaGetSymbolAddress(&p, g_gatout_mol);float* gatout_mol = (float*)p;
    cudaGetSymbolAddress(&p, g_gi_mol);    float* gi_mol = (float*)p;
    cudaGetSymbolAddress(&p, g_gh_mol);    float* gh_mol = (float*)p;
    cudaGetSymbolAddress(&p, g_molout);    float* molout = (float*)p;
    cudaGetSymbolAddress(&p, g_ssrc);      float* ssrc = (float*)p;
    cudaGetSymbolAddress(&p, g_sdst);      float* sdst = (float*)p;
    cudaGetSymbolAddress(&p, g_vd);        float* vd = (float*)p;
    float* outp = (float*)d_out;

    cudaFuncSetAttribute(k_gemm, cudaFuncAttributeMaxDynamicSharedMemorySize, GEMM_SMEM);

    auto gemm = [&](const float* X, const float* W, const float* bias, float* Y,
                    int M, int Nout, const float* avec, float* aout) {
        dim3 grid(296, Nout / 128);
        k_gemm<<<grid, 256, GEMM_SMEM>>>(X, W, bias, Y, M, Nout, avec, aout);
    };

    // ---- CSR build + segment offsets ----
    k_zero_int<<<(NN + 255) / 256, 256>>>(cnt, NN);
    k_hist<<<(EE + 255) / 256, 256>>>(adj_index, cnt);
    k_scan1<<<196, 1024>>>(cnt, rowoff, bsum, NN);
    k_scan2<<<1, 256>>>(bsum, 196);
    k_scan3<<<196, 1024>>>(rowoff, bsum, NN, EE, cursor);
    k_scatter<<<(EE + 255) / 256, 256>>>(adj_index, adj_value, cursor, col, val);
    k_segoff<<<(NN + 255) / 256, 256>>>(ttb, NN, NTTS, ttoff);
    k_segoff<<<(NTTS + 255) / 256, 256>>>(tgb, NTTS, NMOLS, moloff);

    // ---- GCN layer 0: t2 = relu(bn0(A(x@W0^T) + b0)) ----
    gemm(node_attr, W_gcn, nullptr, t1, NN, 128, nullptr, nullptr);
    k_spmm<<<NN / 8, 256>>>(t1, t2, rowoff, col, val, b_gcn, bg, bb, bm, bv, 0, -1, NN);
    // ---- GCN layer 1 (+ fused bn2 of tt stage): t2 = bn2(relu(bn1(...))) ----
    gemm(t2, W_gcn + CC * CC, nullptr, t1, NN, 128, nullptr, nullptr);
    k_spmm<<<NN / 8, 256>>>(t1, t2, rowoff, col, val, b_gcn + CC, bg, bb, bm, bv, 1, 2, NN);

    // ---- tt stage ----
    k_segpool<<<(NTTS * 32 + 255) / 256, 256>>>(t2, meanbn_tt, ttoff, NTTS, bg, bb, bm, bv, 3);
    gemm(t2, Wsrc, nullptr, hs, NN, 128, asrc, ssrc);
    k_vd<<<1, 128>>>(Wdst, adst, vd);
    k_rowdot<<<(NTTS * 32 + 255) / 256, 256>>>(meanbn_tt, vd, sdst, NTTS);
    k_gat<<<(NTTS * 32 + 255) / 256, 256>>>(hs, ssrc, sdst, ttoff, gbias, gatout_tt, NTTS);
    gemm(gatout_tt, Wih, bih, gi_tt, NTTS, 384, nullptr, nullptr);
    gemm(meanbn_tt, Whh, bhh, gh_tt, NTTS, 384, nullptr, nullptr);
    k_gru<<<(NTTS * CC + 255) / 256, 256>>>(gi_tt, gh_tt, meanbn_tt, ttbn, NTTS,
                                            bg, bb, bm, bv, 4, 5);  // bn4 + fused bn5

    // ---- mol stage ----
    k_segpool<<<(NMOLS * 32 + 255) / 256, 256>>>(ttbn, meanbn_mol, moloff, NMOLS, bg, bb, bm, bv, 6);
    gemm(ttbn, Wsrc + CC * CC, nullptr, hs2, NTTS, 128, asrc + CC, ssrc);
    k_vd<<<1, 128>>>(Wdst + CC * CC, adst + CC, vd);
    k_rowdot<<<(NMOLS * 32 + 255) / 256, 256>>>(meanbn_mol, vd, sdst, NMOLS);
    k_gat<<<(NMOLS * 32 + 255) / 256, 256>>>(hs2, ssrc, sdst, moloff, gbias + CC, gatout_mol, NMOLS);
    gemm(gatout_mol, Wih + 3 * CC * CC, bih + 3 * CC, gi_mol, NMOLS, 384, nullptr, nullptr);
    gemm(meanbn_mol, Whh + 3 * CC * CC, bhh + 3 * CC, gh_mol, NMOLS, 384, nullptr, nullptr);
    k_gru<<<(NMOLS * CC + 255) / 256, 256>>>(gi_mol, gh_mol, meanbn_mol, molout, NMOLS,
                                             bg, bb, bm, bv, 7, -1);

    // ---- predictor ----
    k_pred<<<NMOLS, 64>>>(molout, pW1, pb1, pW2, pb2, outp);
}

// round 4
// speedup vs baseline: 1.0104x; 1.0104x over previous
#include <cuda_runtime.h>
#include <cuda_bf16.h>
#include <mma.h>
#include <stdint.h>
#include <stddef.h>
#include <math.h>

using namespace nvcuda;

#define NN 200000
#define EE 1600000
#define CC 128
#define NTTS 20000
#define NMOLS 2000

// ---------------- static device scratch (no allocations allowed) ----------------
__device__ float g_t1[(size_t)NN * CC];
__device__ float g_t2[(size_t)NN * CC];
__device__ float g_hs[(size_t)NN * CC];
__device__ float g_hs2[(size_t)NTTS * CC];
__device__ int   g_cnt[NN];
__device__ int   g_rowoff[NN + 1];
__device__ int   g_cursor[NN];
__device__ int   g_bsum[256];
__device__ int   g_col[EE];
__device__ float g_val[EE];
__device__ int   g_ttoff[NTTS + 1];
__device__ int   g_moloff[NMOLS + 1];
__device__ float g_meanbn_tt[(size_t)NTTS * CC];
__device__ float g_gatout_tt[(size_t)NTTS * CC];
__device__ float g_gi_tt[(size_t)NTTS * 3 * CC];
__device__ float g_gh_tt[(size_t)NTTS * 3 * CC];
__device__ float g_ttbn[(size_t)NTTS * CC];
__device__ float g_meanbn_mol[(size_t)NMOLS * CC];
__device__ float g_gatout_mol[(size_t)NMOLS * CC];
__device__ float g_gi_mol[(size_t)NMOLS * 3 * CC];
__device__ float g_gh_mol[(size_t)NMOLS * 3 * CC];
__device__ float g_molout[(size_t)NMOLS * CC];
__device__ float g_ssrc[NN];
__device__ float g_sdst[NTTS];
__device__ float g_vd[CC];

// ---------------- wmma GEMM: Y[M,Nout] = X[M,128] @ W[Nout,128]^T (+bias)
// fp32-accurate via 3-term bf16 split (Xh*Wh + Xh*Wl + Xl*Wh), fp32 accum.
// 256 threads, one 128x128 output tile per block; optional fused row-dot
// with avec -> aout (for GAT s_src). ----------------
#define LDA 136                       // bf16 elements per row (stride)
#define SM_META 0                     // bias[128] f32 | avec[128] f32 | parts[256] f32
#define SM_TILES 2048
#define AH_OFF (SM_TILES)
#define AL_OFF (AH_OFF + 128 * LDA * 2)
#define BH_OFF (AL_OFF + 128 * LDA * 2)
#define BL_OFF (BH_OFF + 128 * LDA * 2)
#define GEMM_SMEM (BL_OFF + 128 * LDA * 2)   // = 2048 + 4*34816 = 141,312 B
#define C_OFF SM_TILES                // C[128][132] f32 reuses Ah+Al space (67,584 <= 69,632)
#define LDC 132

__global__ __launch_bounds__(256, 1) void k_gemm_tc(
    const float* __restrict__ X, const float* __restrict__ W,
    const float* __restrict__ bias, float* __restrict__ Y, int M, int Nout,
    const float* __restrict__ avec, float* __restrict__ aout) {
    extern __shared__ char smem[];
    float* biasS = reinterpret_cast<float*>(smem + SM_META);
    float* avecS = biasS + 128;
    float* parts = avecS + 128;
    __nv_bfloat16* Ah = reinterpret_cast<__nv_bfloat16*>(smem + AH_OFF);
    __nv_bfloat16* Al = reinterpret_cast<__nv_bfloat16*>(smem + AL_OFF);
    __nv_bfloat16* Bh = reinterpret_cast<__nv_bfloat16*>(smem + BH_OFF);
    __nv_bfloat16* Bl = reinterpret_cast<__nv_bfloat16*>(smem + BL_OFF);
    float* Cs = reinterpret_cast<float*>(smem + C_OFF);

    int tid = threadIdx.x, wid = tid >> 5;
    int tm = blockIdx.x, tn = blockIdx.y;
    int row0 = tm * 128;

    if (tid < 128) {
        biasS[tid] = bias ? bias[tn * 128 + tid] : 0.f;
        avecS[tid] = avec ? avec[tid] : 0.f;
    }
    // W tile rows tn*128..+127 -> Bh/Bl  (row-major, stride LDA)
    for (int i = tid; i < 128 * 32; i += 256) {
        int r = i >> 5, kq = i & 31;
        float4 w = *reinterpret_cast<const float4*>(&W[(size_t)(tn * 128 + r) * 128 + kq * 4]);
        __nv_bfloat16 h0 = __float2bfloat16(w.x), h1 = __float2bfloat16(w.y);
        __nv_bfloat16 h2 = __float2bfloat16(w.z), h3 = __float2bfloat16(w.w);
        __nv_bfloat16* bh = &Bh[r * LDA + kq * 4];
        bh[0] = h0; bh[1] = h1; bh[2] = h2; bh[3] = h3;
        __nv_bfloat16* bl = &Bl[r * LDA + kq * 4];
        bl[0] = __float2bfloat16(w.x - __bfloat162float(h0));
        bl[1] = __float2bfloat16(w.y - __bfloat162float(h1));
        bl[2] = __float2bfloat16(w.z - __bfloat162float(h2));
        bl[3] = __float2bfloat16(w.w - __bfloat162float(h3));
    }
    // X tile rows row0..+127 -> Ah/Al
    for (int i = tid; i < 128 * 32; i += 256) {
        int r = i >> 5, kq = i & 31;
        int gr = row0 + r;
        float4 x = make_float4(0.f, 0.f, 0.f, 0.f);
        if (gr < M) x = *reinterpret_cast<const float4*>(&X[(size_t)gr * 128 + kq * 4]);
        __nv_bfloat16 h0 = __float2bfloat16(x.x), h1 = __float2bfloat16(x.y);
        __nv_bfloat16 h2 = __float2bfloat16(x.z), h3 = __float2bfloat16(x.w);
        __nv_bfloat16* ah = &Ah[r * LDA + kq * 4];
        ah[0] = h0; ah[1] = h1; ah[2] = h2; ah[3] = h3;
        __nv_bfloat16* al = &Al[r * LDA + kq * 4];
        al[0] = __float2bfloat16(x.x - __bfloat162float(h0));
        al[1] = __float2bfloat16(x.y - __bfloat162float(h1));
        al[2] = __float2bfloat16(x.z - __bfloat162float(h2));
        al[3] = __float2bfloat16(x.w - __bfloat162float(h3));
    }
    __syncthreads();

    // warp tiling: 4(m) x 2(n); each warp 32 rows x 64 cols
    int wm = wid >> 1, wn = wid & 1;
    wmma::fragment<wmma::accumulator, 16, 16, 16, float> c[2][4];
#pragma unroll
    for (int i = 0; i < 2; i++)
#pragma unroll
        for (int j = 0; j < 4; j++) wmma::fill_fragment(c[i][j], 0.f);

    const __nv_bfloat16* Aterm[3] = {Ah, Ah, Al};
    const __nv_bfloat16* Bterm[3] = {Bh, Bl, Bh};
#pragma unroll
    for (int t = 0; t < 3; t++) {
        const __nv_bfloat16* As = Aterm[t];
        const __nv_bfloat16* Bs = Bterm[t];
#pragma unroll
        for (int k0 = 0; k0 < 128; k0 += 16) {
            wmma::fragment<wmma::matrix_a, 16, 16, 16, __nv_bfloat16, wmma::row_major> a[2];
            wmma::fragment<wmma::matrix_b, 16, 16, 16, __nv_bfloat16, wmma::col_major> b[4];
#pragma unroll
            for (int i = 0; i < 2; i++)
                wmma::load_matrix_sync(a[i], &As[(wm * 32 + i * 16) * LDA + k0], LDA);
#pragma unroll
            for (int j = 0; j < 4; j++)
                wmma::load_matrix_sync(b[j], &Bs[(wn * 64 + j * 16) * LDA + k0], LDA);
#pragma unroll
            for (int i = 0; i < 2; i++)
#pragma unroll
                for (int j = 0; j < 4; j++) wmma::mma_sync(c[i][j], a[i], b[j], c[i][j]);
        }
    }
    __syncthreads();  // done reading A/B smem; Cs aliases it
#pragma unroll
    for (int i = 0; i < 2; i++)
#pragma unroll
        for (int j = 0; j < 4; j++)
            wmma::store_matrix_sync(&Cs[(wm * 32 + i * 16) * LDC + wn * 64 + j * 16],
                                    c[i][j], LDC, wmma::mem_row_major);
    __syncthreads();

    // epilogue: thread t -> row t/2, col half (t&1)*64; bias + store + fused row-dot
    {
        int r = tid >> 1, ch = (tid & 1) * 64;
        int row = row0 + r;
        float adot = 0.f;
        if (row < M) {
            float* yp = &Y[(size_t)row * Nout + tn * 128 + ch];
#pragma unroll
            for (int j = 0; j < 64; j += 4) {
                float4 v;
                v.x = Cs[r * LDC + ch + j + 0] + biasS[ch + j + 0];
                v.y = Cs[r * LDC + ch + j + 1] + biasS[ch + j + 1];
                v.z = Cs[r * LDC + ch + j + 2] + biasS[ch + j + 2];
                v.w = Cs[r * LDC + ch + j + 3] + biasS[ch + j + 3];
                adot += v.x * avecS[ch + j] + v.y * avecS[ch + j + 1] +
                        v.z * avecS[ch + j + 2] + v.w * avecS[ch + j + 3];
                *reinterpret_cast<float4*>(yp + j) = v;
            }
        }
        if (avec) {
            parts[tid] = adot;
            __syncthreads();
            if ((tid & 1) == 0 && row < M) aout[row] = parts[tid] + parts[tid + 1];
        }
    }
}

// ---------------- small helpers ----------------
__device__ __forceinline__ float bn_apply(float x, int idx, int ch,
                                          const float* g, const float* b,
                                          const float* m, const float* v) {
    float sc = g[idx * CC + ch] * rsqrtf(v[idx * CC + ch] + 1e-5f);
    return (x - m[idx * CC + ch]) * sc + b[idx * CC + ch];
}
__device__ __forceinline__ float warp_max(float v) {
#pragma unroll
    for (int o = 16; o > 0; o >>= 1) v = fmaxf(v, __shfl_xor_sync(0xffffffffu, v, o));
    return v;
}
__device__ __forceinline__ float warp_sum(float v) {
#pragma unroll
    for (int o = 16; o > 0; o >>= 1) v += __shfl_xor_sync(0xffffffffu, v, o);
    return v;
}

// ---------------- CSR build ----------------
__global__ void k_zero_int(int* p, int n) {
    int i = blockIdx.x * blockDim.x + threadIdx.x;
    if (i < n) p[i] = 0;
}
__global__ void k_hist(const int* __restrict__ idx0, int* __restrict__ cnt) {
    int e = blockIdx.x * blockDim.x + threadIdx.x;
    if (e < EE) atomicAdd(&cnt[idx0[e]], 1);
}
__global__ void k_scan1(const int* __restrict__ in, int* __restrict__ out,
                        int* __restrict__ bsum, int n) {
    __shared__ int sm[1024];
    int i = blockIdx.x * 1024 + threadIdx.x;
    int v = (i < n) ? in[i] : 0;
    sm[threadIdx.x] = v;
    __syncthreads();
    for (int off = 1; off < 1024; off <<= 1) {
        int t = (threadIdx.x >= off) ? sm[threadIdx.x - off] : 0;
        __syncthreads();
        sm[threadIdx.x] += t;
        __syncthreads();
    }
    if (i < n) out[i] = sm[threadIdx.x] - v;  // exclusive
    if (threadIdx.x == 1023) bsum[blockIdx.x] = sm[1023];
}
__global__ void k_scan2(int* __restrict__ bsum, int nb) {
    __shared__ int sm[256];
    int v = (threadIdx.x < nb) ? bsum[threadIdx.x] : 0;
    sm[threadIdx.x] = v;
    __syncthreads();
    for (int off = 1; off < 256; off <<= 1) {
        int t = (threadIdx.x >= off) ? sm[threadIdx.x - off] : 0;
        __syncthreads();
        sm[threadIdx.x] += t;
        __syncthreads();
    }
    if (threadIdx.x < nb) bsum[threadIdx.x] = sm[threadIdx.x] - v;  // exclusive
}
__global__ void k_scan3(int* __restrict__ out, const int* __restrict__ bsum,
                        int n, int total, int* __restrict__ cursor) {
    int i = blockIdx.x * 1024 + threadIdx.x;
    if (i < n) {
        int v = out[i] + bsum[blockIdx.x];
        out[i] = v;
        cursor[i] = v;
    }
    if (i == 0) out[n] = total;
}
__global__ void k_scatter(const int* __restrict__ adj, const float* __restrict__ aval,
                          int* __restrict__ cursor, int* __restrict__ col,
                          float* __restrict__ val) {
    int e = blockIdx.x * blockDim.x + threadIdx.x;
    if (e >= EE) return;
    int r = adj[e];
    int p = atomicAdd(&cursor[r], 1);
    col[p] = adj[EE + e];
    val[p] = aval[e];
}
__global__ void k_segoff(const int* __restrict__ seg, int n, int nseg, int* __restrict__ off) {
    int i = blockIdx.x * blockDim.x + threadIdx.x;
    if (i >= n) return;
    int s = seg[i];
    int p = (i == 0) ? -1 : seg[i - 1];
    for (int t = p + 1; t <= s; ++t) off[t] = i;
    if (i == n - 1)
        for (int t = s + 1; t <= nseg; ++t) off[t] = n;
}

// ---------------- SpMM gather (warp/row) + fused bias + BN(+relu)(+BN2) ----------------
__global__ void k_spmm(const float* __restrict__ Xin, float* __restrict__ Y,
                       const int* __restrict__ rowoff, const int* __restrict__ col,
                       const float* __restrict__ val, const float* __restrict__ bias,
                       const float* __restrict__ bg, const float* __restrict__ bb,
                       const float* __restrict__ bm, const float* __restrict__ bv,
                       int bnA, int bnB, int M) {
    int gw = (blockIdx.x * blockDim.x + threadIdx.x) >> 5;
    int lane = threadIdx.x & 31;
    if (gw >= M) return;
    int s = rowoff[gw], e = rowoff[gw + 1];
    float acc[4] = {0.f, 0.f, 0.f, 0.f};
    for (int i = s; i < e; i++) {
        int c = col[i];
        float v = val[i];
        const float* xr = Xin + (size_t)c * CC;
#pragma unroll
        for (int j = 0; j < 4; j++) acc[j] += v * xr[lane + 32 * j];
    }
    float* yr = Y + (size_t)gw * CC;
#pragma unroll
    for (int j = 0; j < 4; j++) {
        int ch = lane + 32 * j;
        float z = acc[j] + bias[ch];
        z = bn_apply(z, bnA, ch, bg, bb, bm, bv);
        z = fmaxf(z, 0.f);
        if (bnB >= 0) z = bn_apply(z, bnB, ch, bg, bb, bm, bv);
        yr[ch] = z;
    }
}

// ---------------- segment sum pool (warp/segment) + relu + BN ----------------
__global__ void k_segpool(const float* __restrict__ X, float* __restrict__ Y,
                          const int* __restrict__ off, int nseg,
                          const float* bg, const float* bb, const float* bm,
                          const float* bv, int bi) {
    int gw = (blockIdx.x * blockDim.x + threadIdx.x) >> 5;
    int lane = threadIdx.x & 31;
    if (gw >= nseg) return;
    int s = off[gw], e = off[gw + 1];
    float acc[4] = {0.f, 0.f, 0.f, 0.f};
    for (int i = s; i < e; i++) {
        const float* xr = X + (size_t)i * CC;
#pragma unroll
        for (int j = 0; j < 4; j++) acc[j] += xr[lane + 32 * j];
    }
    float* yr = Y + (size_t)gw * CC;
#pragma unroll
    for (int j = 0; j < 4; j++) {
        int ch = lane + 32 * j;
        float z = fmaxf(acc[j], 0.f);
        yr[ch] = bn_apply(z, bi, ch, bg, bb, bm, bv);
    }
}

// vd[c] = sum_o adst[o] * Wdst[o,c]
__global__ void k_vd(const float* __restrict__ Wd, const float* __restrict__ ad,
                     float* __restrict__ vd) {
    int c = threadIdx.x;
    float s = 0.f;
    for (int o = 0; o < CC; o++) s += ad[o] * Wd[o * CC + c];
    vd[c] = s;
}
// out[r] = dot(X[r], v)
__global__ void k_rowdot(const float* __restrict__ X, const float* __restrict__ v,
                         float* __restrict__ out, int M) {
    int gw = (blockIdx.x * blockDim.x + threadIdx.x) >> 5;
    int lane = threadIdx.x & 31;
    if (gw >= M) return;
    const float* xr = X + (size_t)gw * CC;
    float s = 0.f;
#pragma unroll
    for (int j = 0; j < 4; j++) s += xr[lane + 32 * j] * v[lane + 32 * j];
    s = warp_sum(s);
    if (lane == 0) out[gw] = s;
}

// ---------------- GAT segment softmax + weighted aggregate + bias + ELU ----------------
__global__ void k_gat(const float* __restrict__ hs, const float* __restrict__ ssrc,
                      const float* __restrict__ sdst, const int* __restrict__ off,
                      const float* __restrict__ bias, float* __restrict__ out, int nseg) {
    int gw = (blockIdx.x * blockDim.x + threadIdx.x) >> 5;
    int lane = threadIdx.x & 31;
    if (gw >= nseg) return;
    int s = off[gw], e = off[gw + 1];
    float sd = sdst[gw];
    float acc[4] = {0.f, 0.f, 0.f, 0.f};
    if (e > s) {
        float mx = -3.402823e38f;
        for (int i = s + lane; i < e; i += 32) {
            float a = ssrc[i] + sd;
            a = a > 0.f ? a : 0.01f * a;
            mx = fmaxf(mx, a);
        }
        mx = warp_max(mx);
        float den = 0.f;
        for (int i = s + lane; i < e; i += 32) {
            float a = ssrc[i] + sd;
            a = a > 0.f ? a : 0.01f * a;
            den += __expf(a - mx);
        }
        den = warp_sum(den);
        float inv = 1.f / den;
        for (int i = s; i < e; i++) {
            float a = ssrc[i] + sd;
            a = a > 0.f ? a : 0.01f * a;
            float w = __expf(a - mx) * inv;
            const float* hr = hs + (size_t)i * CC;
#pragma unroll
            for (int j = 0; j < 4; j++) acc[j] += w * hr[lane + 32 * j];
        }
    }
    float* yr = out + (size_t)gw * CC;
#pragma unroll
    for (int j = 0; j < 4; j++) {
        int ch = lane + 32 * j;
        float v = acc[j] + bias[ch];
        v = v > 0.f ? v : (__expf(v) - 1.f);  // ELU
        yr[ch] = v;
    }
}

// ---------------- GRU gates + relu + BN(+BN2) ----------------
__global__ void k_gru(const float* __restrict__ gi, const float* __restrict__ gh,
                      const float* __restrict__ h, float* __restrict__ out, int M,
                      const float* bg, const float* bb, const float* bm,
                      const float* bv, int bnA, int bnB) {
    int idx = blockIdx.x * blockDim.x + threadIdx.x;
    if (idx >= M * CC) return;
    int t = idx >> 7, c = idx & 127;
    const float* gir = gi + (size_t)t * 3 * CC;
    const float* ghr = gh + (size_t)t * 3 * CC;
    float r = 1.f / (1.f + __expf(-(gir[c] + ghr[c])));
    float z = 1.f / (1.f + __expf(-(gir[CC + c] + ghr[CC + c])));
    float n = tanhf(gir[2 * CC + c] + r * ghr[2 * CC + c]);
    float hv = (1.f - z) * n + z * h[idx];
    float y = fmaxf(hv, 0.f);
    y = bn_apply(y, bnA, c, bg, bb, bm, bv);
    if (bnB >= 0) y = bn_apply(y, bnB, c, bg, bb, bm, bv);
    out[idx] = y;
}

// ---------------- predictor: relu(mol@W1^T+b1)@W2^T+b2 ----------------
__global__ void k_pred(const float* __restrict__ mol, const float* __restrict__ W1,
                       const float* __restrict__ b1, const float* __restrict__ W2,
                       const float* __restrict__ b2, float* __restrict__ out) {
    __shared__ float xr[CC];
    __shared__ float hr[64];
    int m = blockIdx.x, t = threadIdx.x;
    xr[t] = mol[(size_t)m * CC + t];
    xr[t + 64] = mol[(size_t)m * CC + t + 64];
    __syncthreads();
    float s = b1[t];
    for (int c = 0; c < CC; c++) s += W1[t * CC + c] * xr[c];
    s = fmaxf(s, 0.f);
    hr[t] = s * W2[t];
    __syncthreads();
    for (int off = 32; off > 0; off >>= 1) {
        if (t < off) hr[t] += hr[t + off];
        __syncthreads();
    }
    if (t == 0) out[m] = hr[0] + b2[0];
}

// ---------------- host ----------------
extern "C" void kernel_launch(void* const* d_in, const int* in_sizes, int n_in,
                              void* d_out, int out_size) {
    if (n_in < 24) return;
    const float *node_attr, *adj_value, *W_gcn, *b_gcn, *bg, *bb, *bm, *bv;
    const float *Wsrc, *Wdst, *asrc, *adst, *gbias, *Wih, *Whh, *bih, *bhh;
    const float *pW1, *pb1, *pW2, *pb2;
    const int *adj_index, *ttb, *tgb;
    if (in_sizes[1] == EE) {  // reference-signature order
        node_attr = (const float*)d_in[0];  adj_value = (const float*)d_in[1];
        W_gcn = (const float*)d_in[2];      b_gcn = (const float*)d_in[3];
        bg = (const float*)d_in[4];         bb = (const float*)d_in[5];
        bm = (const float*)d_in[6];         bv = (const float*)d_in[7];
        Wsrc = (const float*)d_in[8];       Wdst = (const float*)d_in[9];
        asrc = (const float*)d_in[10];      adst = (const float*)d_in[11];
        gbias = (const float*)d_in[12];     Wih = (const float*)d_in[13];
        Whh = (const float*)d_in[14];       bih = (const float*)d_in[15];
        bhh = (const float*)d_in[16];       pW1 = (const float*)d_in[17];
        pb1 = (const float*)d_in[18];       pW2 = (const float*)d_in[19];
        pb2 = (const float*)d_in[20];       adj_index = (const int*)d_in[21];
        ttb = (const int*)d_in[22];         tgb = (const int*)d_in[23];
    } else {  // setup_inputs dict order
        node_attr = (const float*)d_in[0];  adj_index = (const int*)d_in[1];
        adj_value = (const float*)d_in[2];  ttb = (const int*)d_in[3];
        tgb = (const int*)d_in[4];          W_gcn = (const float*)d_in[5];
        b_gcn = (const float*)d_in[6];      bg = (const float*)d_in[7];
        bb = (const float*)d_in[8];         bm = (const float*)d_in[9];
        bv = (const float*)d_in[10];        Wsrc = (const float*)d_in[11];
        Wdst = (const float*)d_in[12];      asrc = (const float*)d_in[13];
        adst = (const float*)d_in[14];      gbias = (const float*)d_in[15];
        Wih = (const float*)d_in[16];       Whh = (const float*)d_in[17];
        bih = (const float*)d_in[18];       bhh = (const float*)d_in[19];
        pW1 = (const float*)d_in[20];       pb1 = (const float*)d_in[21];
        pW2 = (const float*)d_in[22];       pb2 = (const float*)d_in[23];
    }

    void* p;
    cudaGetSymbolAddress(&p, g_t1);        float* t1 = (float*)p;
    cudaGetSymbolAddress(&p, g_t2);        float* t2 = (float*)p;
    cudaGetSymbolAddress(&p, g_hs);        float* hs = (float*)p;
    cudaGetSymbolAddress(&p, g_hs2);       float* hs2 = (float*)p;
    cudaGetSymbolAddress(&p, g_cnt);       int* cnt = (int*)p;
    cudaGetSymbolAddress(&p, g_rowoff);    int* rowoff = (int*)p;
    cudaGetSymbolAddress(&p, g_cursor);    int* cursor = (int*)p;
    cudaGetSymbolAddress(&p, g_bsum);      int* bsum = (int*)p;
    cudaGetSymbolAddress(&p, g_col);       int* col = (int*)p;
    cudaGetSymbolAddress(&p, g_val);       float* val = (float*)p;
    cudaGetSymbolAddress(&p, g_ttoff);     int* ttoff = (int*)p;
    cudaGetSymbolAddress(&p, g_moloff);    int* moloff = (int*)p;
    cudaGetSymbolAddress(&p, g_meanbn_tt); float* meanbn_tt = (float*)p;
    cudaGetSymbolAddress(&p, g_gatout_tt); float* gatout_tt = (float*)p;
    cudaGetSymbolAddress(&p, g_gi_tt);     float* gi_tt = (float*)p;
    cudaGetSymbolAddress(&p, g_gh_tt);     float* gh_tt = (float*)p;
    cudaGetSymbolAddress(&p, g_ttbn);      float* ttbn = (float*)p;
    cudaGetSymbolAddress(&p, g_meanbn_mol);float* meanbn_mol = (float*)p;
    cudaGetSymbolAddress(&p, g_gatout_mol);float* gatout_mol = (float*)p;
    cudaGetSymbolAddress(&p, g_gi_mol);    float* gi_mol = (float*)p;
    cudaGetSymbolAddress(&p, g_gh_mol);    float* gh_mol = (float*)p;
    cudaGetSymbolAddress(&p, g_molout);    float* molout = (float*)p;
    cudaGetSymbolAddress(&p, g_ssrc);      float* ssrc = (float*)p;
    cudaGetSymbolAddress(&p, g_sdst);      float* sdst = (float*)p;
    cudaGetSymbolAddress(&p, g_vd);        float* vd = (float*)p;
    float* outp = (float*)d_out;

    cudaFuncSetAttribute(k_gemm_tc, cudaFuncAttributeMaxDynamicSharedMemorySize, GEMM_SMEM);

    auto gemm = [&](const float* X, const float* W, const float* bias, float* Y,
                    int M, int Nout, const float* avec, float* aout) {
        dim3 grid((M + 127) / 128, Nout / 128);
        k_gemm_tc<<<grid, 256, GEMM_SMEM>>>(X, W, bias, Y, M, Nout, avec, aout);
    };

    // ---- CSR build + segment offsets ----
    k_zero_int<<<(NN + 255) / 256, 256>>>(cnt, NN);
    k_hist<<<(EE + 255) / 256, 256>>>(adj_index, cnt);
    k_scan1<<<196, 1024>>>(cnt, rowoff, bsum, NN);
    k_scan2<<<1, 256>>>(bsum, 196);
    k_scan3<<<196, 1024>>>(rowoff, bsum, NN, EE, cursor);
    k_scatter<<<(EE + 255) / 256, 256>>>(adj_index, adj_value, cursor, col, val);
    k_segoff<<<(NN + 255) / 256, 256>>>(ttb, NN, NTTS, ttoff);
    k_segoff<<<(NTTS + 255) / 256, 256>>>(tgb, NTTS, NMOLS, moloff);

    // ---- GCN layer 0: t2 = relu(bn0(A(x@W0^T) + b0)) ----
    gemm(node_attr, W_gcn, nullptr, t1, NN, 128, nullptr, nullptr);
    k_spmm<<<NN / 8, 256>>>(t1, t2, rowoff, col, val, b_gcn, bg, bb, bm, bv, 0, -1, NN);
    // ---- GCN layer 1 (+ fused bn2 of tt stage): t2 = bn2(relu(bn1(...))) ----
    gemm(t2, W_gcn + CC * CC, nullptr, t1, NN, 128, nullptr, nullptr);
    k_spmm<<<NN / 8, 256>>>(t1, t2, rowoff, col, val, b_gcn + CC, bg, bb, bm, bv, 1, 2, NN);

    // ---- tt stage ----
    k_segpool<<<(NTTS * 32 + 255) / 256, 256>>>(t2, meanbn_tt, ttoff, NTTS, bg, bb, bm, bv, 3);
    gemm(t2, Wsrc, nullptr, hs, NN, 128, asrc, ssrc);
    k_vd<<<1, 128>>>(Wdst, adst, vd);
    k_rowdot<<<(NTTS * 32 + 255) / 256, 256>>>(meanbn_tt, vd, sdst, NTTS);
    k_gat<<<(NTTS * 32 + 255) / 256, 256>>>(hs, ssrc, sdst, ttoff, gbias, gatout_tt, NTTS);
    gemm(gatout_tt, Wih, bih, gi_tt, NTTS, 384, nullptr, nullptr);
    gemm(meanbn_tt, Whh, bhh, gh_tt, NTTS, 384, nullptr, nullptr);
    k_gru<<<(NTTS * CC + 255) / 256, 256>>>(gi_tt, gh_tt, meanbn_tt, ttbn, NTTS,
                                            bg, bb, bm, bv, 4, 5);  // bn4 + fused bn5

    // ---- mol stage ----
    k_segpool<<<(NMOLS * 32 + 255) / 256, 256>>>(ttbn, meanbn_mol, moloff, NMOLS, bg, bb, bm, bv, 6);
    gemm(ttbn, Wsrc + CC * CC, nullptr, hs2, NTTS, 128, asrc + CC, ssrc);
    k_vd<<<1, 128>>>(Wdst + CC * CC, adst + CC, vd);
    k_rowdot<<<(NMOLS * 32 + 255) / 256, 256>>>(meanbn_mol, vd, sdst, NMOLS);
    k_gat<<<(NMOLS * 32 + 255) / 256, 256>>>(hs2, ssrc, sdst, moloff, gbias + CC, gatout_mol, NMOLS);
    gemm(gatout_mol, Wih + 3 * CC * CC, bih + 3 * CC, gi_mol, NMOLS, 384, nullptr, nullptr);
    gemm(meanbn_mol, Whh + 3 * CC * CC, bhh + 3 * CC, gh_mol, NMOLS, 384, nullptr, nullptr);
    k_gru<<<(NMOLS * CC + 255) / 256, 256>>>(gi_mol, gh_mol, meanbn_mol, molout, NMOLS,
                                             bg, bb, bm, bv, 7, -1);

    // ---- predictor ----
    k_pred<<<NMOLS, 64>>>(molout, pW1, pb1, pW2, pb2, outp);
}